// round 7
// baseline (speedup 1.0000x reference)
#include <cuda_runtime.h>
#include <cuda_bf16.h>
#include <stdint.h>
#include <math.h>

// Problem constants
#define TT 65536
#define DD 256
#define LL 3

// GEMM tiling
#define BM 128
#define BN 64
#define KC 32
#define NCHUNK (DD / KC)   // 8

#define ROWB 80                     // padded smem row stride (bytes)
#define PLA (128 * ROWB)            // A plane: 10240 B
#define PLB (64 * ROWB)             // B plane: 5120 B
#define BOFF (6 * PLA)              // 61440
#define BUFSZ (6 * PLA + 6 * PLB)   // 92160
#define SM_BIAS (2 * BUFSZ)         // 184320
#define SMEM_TOTAL (SM_BIAS + 512 + 64)
#define SM_SEG (2 * 128 * 68 * 4)   // seg aggregates after smA/smB (69632)

// Scan blocking (block = gemm CTA M-tile)
#define CS 128
#define NB (TT / CS)  // 512

// ---------------------------------------------------------------------------
// Scratch
// ---------------------------------------------------------------------------
__device__ __align__(256) float g_af[TT * DD];
__device__ __align__(256) float g_bf[TT * DD];
__device__ __align__(256) float g_ab[TT * DD];
__device__ __align__(256) float g_bb[TT * DD];
__device__ __align__(256) float g_aggA_f[NB * DD];
__device__ __align__(256) float g_aggB_f[NB * DD];
__device__ __align__(256) float g_hex_f[NB * DD];
__device__ __align__(256) float g_aggA_b[NB * DD];
__device__ __align__(256) float g_aggB_b[NB * DD];
__device__ __align__(256) float g_hex_b[NB * DD];
// bf16 hi/lo operand planes
__device__ __align__(256) __nv_bfloat16 g_xh[TT * DD];
__device__ __align__(256) __nv_bfloat16 g_xl[TT * DD];
__device__ __align__(256) __nv_bfloat16 g_qh[TT * DD];
__device__ __align__(256) __nv_bfloat16 g_ql[TT * DD];
__device__ __align__(256) __nv_bfloat16 g_uh[TT * DD];
__device__ __align__(256) __nv_bfloat16 g_ul[TT * DD];
// pre-transposed hi/lo-split weights: [5 layer-dirs][3 mats][256 n][256 k]
__device__ __align__(256) __nv_bfloat16 g_whi[5 * 3 * DD * DD];
__device__ __align__(256) __nv_bfloat16 g_wlo[5 * 3 * DD * DD];
// layer-0 effective h-bias (bh + Whq^T q0): [2 dirs][256]
__device__ __align__(256) float g_bheff[2 * DD];

__device__ __forceinline__ float tanh_fast(float v) {
    float r;
    asm("tanh.approx.f32 %0, %1;" : "=f"(r) : "f"(v));
    return r;
}
__device__ __forceinline__ uint32_t smem_u32(const void* p) {
    uint32_t a;
    asm("{ .reg .u64 t; cvta.to.shared.u64 t, %1; cvt.u32.u64 %0, t; }"
        : "=r"(a) : "l"(p));
    return a;
}
__device__ __forceinline__ void ldsm4(uint32_t addr, uint32_t* r) {
    asm volatile("ldmatrix.sync.aligned.m8n8.x4.shared.b16 {%0,%1,%2,%3}, [%4];"
                 : "=r"(r[0]), "=r"(r[1]), "=r"(r[2]), "=r"(r[3]) : "r"(addr));
}
__device__ __forceinline__ void mma16816(float* c, const uint32_t* a,
                                         const uint32_t* b) {
    asm volatile(
        "mma.sync.aligned.m16n8k16.row.col.f32.bf16.bf16.f32 "
        "{%0,%1,%2,%3}, {%4,%5,%6,%7}, {%8,%9}, {%0,%1,%2,%3};"
        : "+f"(c[0]), "+f"(c[1]), "+f"(c[2]), "+f"(c[3])
        : "r"(a[0]), "r"(a[1]), "r"(a[2]), "r"(a[3]), "r"(b[0]), "r"(b[1]));
}
__device__ __forceinline__ void cpa16(uint32_t dst, const void* src) {
    asm volatile("cp.async.cg.shared.global [%0], [%1], 16;"
                 :: "r"(dst), "l"(src) : "memory");
}

// hi/lo bf16 split of a float4; one 8B store each
__device__ __forceinline__ void split_store(float4 v, char* hi, char* lo) {
    __nv_bfloat16 h0 = __float2bfloat16_rn(v.x);
    __nv_bfloat16 h1 = __float2bfloat16_rn(v.y);
    __nv_bfloat16 h2 = __float2bfloat16_rn(v.z);
    __nv_bfloat16 h3 = __float2bfloat16_rn(v.w);
    __nv_bfloat162 H0; H0.x = h0; H0.y = h1;
    __nv_bfloat162 H1; H1.x = h2; H1.y = h3;
    __nv_bfloat162 L0, L1;
    L0.x = __float2bfloat16_rn(v.x - __bfloat162float(h0));
    L0.y = __float2bfloat16_rn(v.y - __bfloat162float(h1));
    L1.x = __float2bfloat16_rn(v.z - __bfloat162float(h2));
    L1.y = __float2bfloat16_rn(v.w - __bfloat162float(h3));
    uint2 H; H.x = *(uint32_t*)&H0; H.y = *(uint32_t*)&H1;
    uint2 L; L.x = *(uint32_t*)&L0; L.y = *(uint32_t*)&L1;
    *(uint2*)hi = H;
    *(uint2*)lo = L;
}

// ---------------------------------------------------------------------------
// prep_weights: transpose to [n][k], split hi/lo bf16.
// ---------------------------------------------------------------------------
__global__ void prep_weights(const float* __restrict__ Wz,
                             const float* __restrict__ Wh,
                             __nv_bfloat16* __restrict__ whi,
                             __nv_bfloat16* __restrict__ wlo) {
    int n = blockIdx.x, m = blockIdx.y, k = threadIdx.x;
    float v = (m == 0) ? Wz[k * DD + n]
            : (m == 1) ? Wh[k * DD + n]
                       : Wh[(DD + k) * DD + n];
    __nv_bfloat16 hi = __float2bfloat16_rn(v);
    __nv_bfloat16 lo = __float2bfloat16_rn(v - __bfloat162float(hi));
    whi[(m * DD + n) * DD + k] = hi;
    wlo[(m * DD + n) * DD + k] = lo;
}

// ---------------------------------------------------------------------------
// prep_x: split story -> (xh,xl); u0 = story*q0 -> (uh,ul)
// ---------------------------------------------------------------------------
__global__ void prep_x(const float* __restrict__ story,
                       const float* __restrict__ question,
                       __nv_bfloat16* __restrict__ xh, __nv_bfloat16* __restrict__ xl,
                       __nv_bfloat16* __restrict__ uh, __nv_bfloat16* __restrict__ ul)
{
    int idx = blockIdx.x * 256 + threadIdx.x;   // float4 index
    int c = (idx & 63) << 2;
    float4 xv = ((const float4*)story)[idx];
    float4 qv = *(const float4*)(question + c);
    float4 uv = make_float4(xv.x * qv.x, xv.y * qv.y, xv.z * qv.z, xv.w * qv.w);
    split_store(xv, (char*)xh + (size_t)idx * 8, (char*)xl + (size_t)idx * 8);
    split_store(uv, (char*)uh + (size_t)idx * 8, (char*)ul + (size_t)idx * 8);
}

// ---------------------------------------------------------------------------
// prep_bias: bheff[dir][n] = bh[n] + sum_k q0[k] * Whq[k][n]   (layer 0)
// ---------------------------------------------------------------------------
__global__ void prep_bias(const float* __restrict__ question,
                          const float* __restrict__ Wh_f, const float* __restrict__ bh_f,
                          const float* __restrict__ Wh_b, const float* __restrict__ bh_b,
                          float* __restrict__ bheff)
{
    __shared__ float red[256];
    int n = blockIdx.x, k = threadIdx.x;
    const float* Wh = blockIdx.y ? Wh_b : Wh_f;
    const float* bh = blockIdx.y ? bh_b : bh_f;
    red[k] = question[k] * Wh[(DD + k) * DD + n];
    __syncthreads();
    for (int s = 128; s > 0; s >>= 1) {
        if (k < s) red[k] += red[k + s];
        __syncthreads();
    }
    if (k == 0) bheff[blockIdx.y * DD + n] = bh[n] + red[0];
}

// ---------------------------------------------------------------------------
// Fused GEMM (mma.sync bf16, 3-pass hi/lo) + activation + block-local scan.
// Outputs: outA/outB = block-local (Aprefix, h_local); aggA/aggB per block.
// ---------------------------------------------------------------------------
__global__ void __launch_bounds__(256, 1) gemm_mma(
    const __nv_bfloat16* __restrict__ uh, const __nv_bfloat16* __restrict__ ul,
    const __nv_bfloat16* __restrict__ xh, const __nv_bfloat16* __restrict__ xl,
    const __nv_bfloat16* __restrict__ qh, const __nv_bfloat16* __restrict__ ql,
    int use_q, int rev,
    const __nv_bfloat16* __restrict__ whi, const __nv_bfloat16* __restrict__ wlo,
    const float* __restrict__ bz, const float* __restrict__ bh,
    float* __restrict__ outA, float* __restrict__ outB,
    float* __restrict__ aggA, float* __restrict__ aggB)
{
    extern __shared__ char smem[];
    const int tid = threadIdx.x;
    const int wid = tid >> 5;
    const int lane = tid & 31;
    const int wm = wid & 3;
    const int wn = wid >> 2;
    const int tbase = blockIdx.x * BM;
    const int nbase = blockIdx.y * BN;
    const uint32_t sb = smem_u32(smem);

    float* bzs = (float*)(smem + SM_BIAS);
    float* bhs = bzs + 64;
    if (tid < 64) {
        bzs[tid] = bz[nbase + tid];
        bhs[tid] = bh[nbase + tid];
    }

    const __nv_bfloat16* a6[6] = { uh, ul, xh, xl, qh, ql };
    const __nv_bfloat16* w6[6] = {
        whi, wlo, whi + DD * DD, wlo + DD * DD, whi + 2 * DD * DD, wlo + 2 * DD * DD
    };
    const int np = use_q ? 6 : 4;

    float acc[2][2][4][4];
    #pragma unroll
    for (int zh = 0; zh < 2; ++zh)
        #pragma unroll
        for (int mt = 0; mt < 2; ++mt)
            #pragma unroll
            for (int nt = 0; nt < 4; ++nt)
                #pragma unroll
                for (int j = 0; j < 4; ++j) acc[zh][mt][nt][j] = 0.f;

    const int jrow = tid >> 2;   // 0..63
    const int seg4 = tid & 3;    // 16B segment within 64B k-slice

    auto stage_chunk = [&](int c) {
        const uint32_t base = sb + (c & 1) * BUFSZ;
        const int k0 = c * KC;
        #pragma unroll
        for (int p = 0; p < 6; ++p) {
            if (p < np) {
                #pragma unroll
                for (int h = 0; h < 2; ++h) {
                    int row = jrow + h * 64;
                    int tg = rev ? (TT - 1 - (tbase + row)) : (tbase + row);
                    cpa16(base + p * PLA + row * ROWB + seg4 * 16,
                          a6[p] + (size_t)tg * DD + k0 + seg4 * 8);
                }
                cpa16(base + BOFF + p * PLB + jrow * ROWB + seg4 * 16,
                      w6[p] + (size_t)(nbase + jrow) * DD + k0 + seg4 * 8);
            }
        }
    };

    stage_chunk(0);
    asm volatile("cp.async.commit_group;" ::: "memory");

    const int r = lane & 7, g = lane >> 3;
    #pragma unroll 1
    for (int c = 0; c < NCHUNK; ++c) {
        asm volatile("cp.async.wait_group 0;" ::: "memory");
        __syncthreads();
        if (c < NCHUNK - 1) {
            stage_chunk(c + 1);
            asm volatile("cp.async.commit_group;" ::: "memory");
        }
        const uint32_t abuf = sb + (c & 1) * BUFSZ;
        const uint32_t bbuf = abuf + BOFF;

        #pragma unroll
        for (int ks = 0; ks < 2; ++ks) {
            const uint32_t kso = ks * 32;
            uint32_t af[6][2][4];
            #pragma unroll
            for (int o = 0; o < 6; ++o)
                if (o < np) {
                    #pragma unroll
                    for (int mt = 0; mt < 2; ++mt) {
                        uint32_t addr = abuf + o * PLA
                            + (wm * 32 + mt * 16 + (g & 1) * 8 + r) * ROWB
                            + (g >> 1) * 16 + kso;
                        ldsm4(addr, af[o][mt]);
                    }
                }
            uint32_t bf[6][4][2];
            #pragma unroll
            for (int m6 = 0; m6 < 6; ++m6)
                if (m6 < np) {
                    #pragma unroll
                    for (int j = 0; j < 2; ++j) {
                        uint32_t tmp[4];
                        uint32_t addr = bbuf + m6 * PLB
                            + (wn * 32 + (2 * j + (g >> 1)) * 8 + r) * ROWB
                            + (g & 1) * 16 + kso;
                        ldsm4(addr, tmp);
                        bf[m6][2 * j][0] = tmp[0]; bf[m6][2 * j][1] = tmp[1];
                        bf[m6][2 * j + 1][0] = tmp[2]; bf[m6][2 * j + 1][1] = tmp[3];
                    }
                }
            #pragma unroll
            for (int mt = 0; mt < 2; ++mt)
                #pragma unroll
                for (int nt = 0; nt < 4; ++nt) {
                    mma16816(acc[0][mt][nt], af[0][mt], bf[0][nt]);
                    mma16816(acc[0][mt][nt], af[0][mt], bf[1][nt]);
                    mma16816(acc[0][mt][nt], af[1][mt], bf[0][nt]);
                    mma16816(acc[1][mt][nt], af[2][mt], bf[2][nt]);
                    mma16816(acc[1][mt][nt], af[2][mt], bf[3][nt]);
                    mma16816(acc[1][mt][nt], af[3][mt], bf[2][nt]);
                    if (use_q) {
                        mma16816(acc[1][mt][nt], af[4][mt], bf[4][nt]);
                        mma16816(acc[1][mt][nt], af[4][mt], bf[5][nt]);
                        mma16816(acc[1][mt][nt], af[5][mt], bf[4][nt]);
                    }
                }
        }
    }

    // --- epilogue: activations -> smem transpose ---------------------------
    float* smA = (float*)smem;              // [128][68]
    float* smB = smA + 128 * 68;
    #pragma unroll
    for (int mt = 0; mt < 2; ++mt)
        #pragma unroll
        for (int nt = 0; nt < 4; ++nt) {
            int col = wn * 32 + nt * 8 + 2 * (lane & 3);
            int row0 = wm * 32 + mt * 16 + (lane >> 2);
            #pragma unroll
            for (int h8 = 0; h8 < 2; ++h8) {
                int row = row0 + h8 * 8;
                float z0 = 0.5f * tanh_fast(0.5f * (acc[0][mt][nt][2*h8+0] + bzs[col]))   + 0.5f;
                float z1 = 0.5f * tanh_fast(0.5f * (acc[0][mt][nt][2*h8+1] + bzs[col+1])) + 0.5f;
                float t0 = tanh_fast(acc[1][mt][nt][2*h8+0] + bhs[col]);
                float t1 = tanh_fast(acc[1][mt][nt][2*h8+1] + bhs[col+1]);
                *(float2*)(smA + row * 68 + col) = make_float2(1.f - z0, 1.f - z1);
                *(float2*)(smB + row * 68 + col) = make_float2(z0 * t0, z1 * t1);
            }
        }
    __syncthreads();

    // --- fused block-local scan over 128 rows ------------------------------
    float* segA = (float*)(smem + SM_SEG);        // [4][64]
    float* segB = segA + 4 * 64;
    {
        const int col = tid & 63;
        const int sg = tid >> 6;                   // 0..3
        const int rbase = sg * 32;
        float Ap = 1.f, hl = 0.f;
        #pragma unroll 8
        for (int i = 0; i < 32; ++i) {
            int off = (rbase + i) * 68 + col;
            float a = smA[off], b = smB[off];
            Ap *= a;
            hl = fmaf(a, hl, b);
            smA[off] = Ap;
            smB[off] = hl;
        }
        segA[sg * 64 + col] = Ap;
        segB[sg * 64 + col] = hl;
        __syncthreads();
        float Ain = 1.f, Hin = 0.f;
        #pragma unroll
        for (int s = 0; s < 3; ++s)
            if (s < sg) {
                float sa = segA[s * 64 + col], sbv = segB[s * 64 + col];
                Ain *= sa;
                Hin = fmaf(sa, Hin, sbv);
            }
        #pragma unroll 8
        for (int i = 0; i < 32; ++i) {
            int off = (rbase + i) * 68 + col;
            float Al = smA[off], Bl = smB[off];
            smA[off] = Ain * Al;
            smB[off] = fmaf(Al, Hin, Bl);
        }
        if (sg == 3) {
            aggA[(size_t)blockIdx.x * DD + nbase + col] = Ain * Ap;
            aggB[(size_t)blockIdx.x * DD + nbase + col] = fmaf(Ap, Hin, hl);
        }
    }
    __syncthreads();

    // --- coalesced global stores -------------------------------------------
    #pragma unroll
    for (int it = 0; it < 8; ++it) {
        int j = tid + it * 256;
        int row = j >> 4, cf = j & 15;
        size_t go = (size_t)(tbase + row) * DD + nbase + cf * 4;
        *(float4*)(outA + go) = *(const float4*)(smA + row * 68 + cf * 4);
        *(float4*)(outB + go) = *(const float4*)(smB + row * 68 + cf * 4);
    }
}

// ---------------------------------------------------------------------------
// scan2: exclusive scan over NB block aggregates.
// ---------------------------------------------------------------------------
__global__ void scan2_kernel(const float* __restrict__ aggA,
                             const float* __restrict__ aggB,
                             float* __restrict__ hex)
{
    const int d = threadIdx.x;
    float H = 0.f;
    for (int b = 0; b < NB; ++b) {
        hex[b * DD + d] = H;
        H = fmaf(aggA[b * DD + d], H, aggB[b * DD + d]);
    }
}

// ---------------------------------------------------------------------------
// combine: q = h_fwd + h_bwd_rev; write (qh,ql) and (uh,ul) with u = story*q.
// ---------------------------------------------------------------------------
__global__ void combine_kernel(
    const float* __restrict__ Af, const float* __restrict__ Bf,
    const float* __restrict__ hexf,
    const float* __restrict__ Ab, const float* __restrict__ Bb,
    const float* __restrict__ hexb,
    const float* __restrict__ story,
    __nv_bfloat16* __restrict__ qh, __nv_bfloat16* __restrict__ ql,
    __nv_bfloat16* __restrict__ uh, __nv_bfloat16* __restrict__ ul)
{
    int idx = blockIdx.x * blockDim.x + threadIdx.x;   // float4 index
    int t = idx >> 6;
    int c = (idx & 63) << 2;
    int tr = TT - 1 - t;
    int blf = t >> 7;        // CS = 128
    int blb = tr >> 7;

    float4 af = *(const float4*)(Af + (size_t)t * DD + c);
    float4 bfv = *(const float4*)(Bf + (size_t)t * DD + c);
    float4 hf = *(const float4*)(hexf + (size_t)blf * DD + c);
    float4 ab = *(const float4*)(Ab + (size_t)tr * DD + c);
    float4 bb = *(const float4*)(Bb + (size_t)tr * DD + c);
    float4 hb = *(const float4*)(hexb + (size_t)blb * DD + c);

    float4 q4;
    q4.x = fmaf(af.x, hf.x, bfv.x) + fmaf(ab.x, hb.x, bb.x);
    q4.y = fmaf(af.y, hf.y, bfv.y) + fmaf(ab.y, hb.y, bb.y);
    q4.z = fmaf(af.z, hf.z, bfv.z) + fmaf(ab.z, hb.z, bb.z);
    q4.w = fmaf(af.w, hf.w, bfv.w) + fmaf(ab.w, hb.w, bb.w);

    float4 xv = *(const float4*)(story + (size_t)t * DD + c);
    float4 u4 = make_float4(xv.x * q4.x, xv.y * q4.y, xv.z * q4.z, xv.w * q4.w);

    split_store(q4, (char*)qh + (size_t)idx * 8, (char*)ql + (size_t)idx * 8);
    split_store(u4, (char*)uh + (size_t)idx * 8, (char*)ul + (size_t)idx * 8);
}

__global__ void final_kernel(const float* __restrict__ Af,
                             const float* __restrict__ Bf,
                             const float* __restrict__ hexf,
                             float* __restrict__ out)
{
    const int d = threadIdx.x;
    out[d] = fmaf(Af[(size_t)(TT - 1) * DD + d], hexf[(size_t)(NB - 1) * DD + d],
                  Bf[(size_t)(TT - 1) * DD + d]);
}

// ---------------------------------------------------------------------------
// Host orchestration
// ---------------------------------------------------------------------------
extern "C" void kernel_launch(void* const* d_in, const int* in_sizes, int n_in,
                              void* d_out, int out_size)
{
    const float* story    = (const float*)d_in[0];
    const float* question = (const float*)d_in[1];
    const float* Wz_f = (const float*)d_in[2];
    const float* bz_f = (const float*)d_in[3];
    const float* Wh_f = (const float*)d_in[4];
    const float* bh_f = (const float*)d_in[5];
    const float* Wz_b = (const float*)d_in[6];
    const float* bz_b = (const float*)d_in[7];
    const float* Wh_b = (const float*)d_in[8];
    const float* bh_b = (const float*)d_in[9];
    float* out = (float*)d_out;

    float *af, *bf, *ab, *bb, *aggAf, *aggBf, *hexf, *aggAb, *aggBb, *hexb, *bheff;
    __nv_bfloat16 *whi, *wlo, *xh, *xl, *qh, *ql, *uh, *ul;
    cudaGetSymbolAddress((void**)&af,    g_af);
    cudaGetSymbolAddress((void**)&bf,    g_bf);
    cudaGetSymbolAddress((void**)&ab,    g_ab);
    cudaGetSymbolAddress((void**)&bb,    g_bb);
    cudaGetSymbolAddress((void**)&aggAf, g_aggA_f);
    cudaGetSymbolAddress((void**)&aggBf, g_aggB_f);
    cudaGetSymbolAddress((void**)&hexf,  g_hex_f);
    cudaGetSymbolAddress((void**)&aggAb, g_aggA_b);
    cudaGetSymbolAddress((void**)&aggBb, g_aggB_b);
    cudaGetSymbolAddress((void**)&hexb,  g_hex_b);
    cudaGetSymbolAddress((void**)&whi,   g_whi);
    cudaGetSymbolAddress((void**)&wlo,   g_wlo);
    cudaGetSymbolAddress((void**)&xh,    g_xh);
    cudaGetSymbolAddress((void**)&xl,    g_xl);
    cudaGetSymbolAddress((void**)&qh,    g_qh);
    cudaGetSymbolAddress((void**)&ql,    g_ql);
    cudaGetSymbolAddress((void**)&uh,    g_uh);
    cudaGetSymbolAddress((void**)&ul,    g_ul);
    cudaGetSymbolAddress((void**)&bheff, g_bheff);

    static int smem_set = 0;
    if (!smem_set) {
        cudaFuncSetAttribute(gemm_mma, cudaFuncAttributeMaxDynamicSharedMemorySize,
                             SMEM_TOTAL);
        smem_set = 1;
    }

    // Preprocess weights: slots 0..2 = fwd L0..L2, 3..4 = bwd L0..L1
    const int MSZ = 3 * DD * DD;
    for (int l = 0; l < LL; ++l)
        prep_weights<<<dim3(DD, 3), 256>>>(Wz_f + l * DD * DD, Wh_f + l * 2 * DD * DD,
                                           whi + l * MSZ, wlo + l * MSZ);
    for (int l = 0; l < LL - 1; ++l)
        prep_weights<<<dim3(DD, 3), 256>>>(Wz_b + l * DD * DD, Wh_b + l * 2 * DD * DD,
                                           whi + (3 + l) * MSZ, wlo + (3 + l) * MSZ);
    prep_x<<<TT * DD / 4 / 256, 256>>>(story, question, xh, xl, uh, ul);
    prep_bias<<<dim3(DD, 2), 256>>>(question, Wh_f, bh_f, Wh_b, bh_b, bheff);

    dim3 ggrid(TT / BM, DD / BN);  // (512, 4)

    for (int l = 0; l < LL; ++l) {
        const int uq = (l == 0) ? 0 : 1;
        const float* bhf_eff = (l == 0) ? bheff : bh_f + l * DD;
        const float* bhb_eff = (l == 0) ? bheff + DD : bh_b + l * DD;

        gemm_mma<<<ggrid, 256, SMEM_TOTAL>>>(
            uh, ul, xh, xl, qh, ql, uq, 0,
            whi + l * MSZ, wlo + l * MSZ,
            bz_f + l * DD, bhf_eff, af, bf, aggAf, aggBf);
        scan2_kernel<<<1, 256>>>(aggAf, aggBf, hexf);

        if (l < LL - 1) {
            gemm_mma<<<ggrid, 256, SMEM_TOTAL>>>(
                uh, ul, xh, xl, qh, ql, uq, 1,
                whi + (3 + l) * MSZ, wlo + (3 + l) * MSZ,
                bz_b + l * DD, bhb_eff, ab, bb, aggAb, aggBb);
            scan2_kernel<<<1, 256>>>(aggAb, aggBb, hexb);

            combine_kernel<<<TT * DD / 4 / 256, 256>>>(
                af, bf, hexf, ab, bb, hexb, story, qh, ql, uh, ul);
        } else {
            final_kernel<<<1, 256>>>(af, bf, hexf, out);
        }
    }
}